// round 3
// baseline (speedup 1.0000x reference)
#include <cuda_runtime.h>
#include <cstdint>
#include <cstddef>

#define Bc 8
#define Nc 384
#define Dc 256
#define Hc 1024
#define MR (Bc*Nc)   // 3072

__device__ float g_hidden[(size_t)MR * Hc];   // relu(fc1(x))  3072x1024
__device__ float g_y[(size_t)MR * Dc];        // x_hat * w     3072x256
__device__ float g_sumw;

// ---- packed f32x2 helpers --------------------------------------------------
__device__ __forceinline__ uint64_t pk2(float x, float y) {
    uint64_t r; asm("mov.b64 %0,{%1,%2};" : "=l"(r) : "f"(x), "f"(y)); return r;
}
__device__ __forceinline__ float2 upk2(uint64_t v) {
    float2 r; asm("mov.b64 {%0,%1},%2;" : "=f"(r.x), "=f"(r.y) : "l"(v)); return r;
}
__device__ __forceinline__ uint64_t fma2(uint64_t a, uint64_t b, uint64_t c) {
    uint64_t d; asm("fma.rn.f32x2 %0,%1,%2,%3;" : "=l"(d) : "l"(a), "l"(b), "l"(c)); return d;
}
__device__ __forceinline__ uint64_t add2(uint64_t a, uint64_t b) {
    uint64_t d; asm("add.rn.f32x2 %0,%1,%2;" : "=l"(d) : "l"(a), "l"(b)); return d;
}
#define ABS2 0x7FFFFFFF7FFFFFFFull

// ---------------------------------------------------------------- sum(w)
__global__ void sumw_kernel(const float* __restrict__ w) {
    __shared__ float sm[8];
    int t = threadIdx.x;
    float v = w[t];
    #pragma unroll
    for (int off = 16; off; off >>= 1) v += __shfl_xor_sync(0xffffffffu, v, off);
    if ((t & 31) == 0) sm[t >> 5] = v;
    __syncthreads();
    if (t == 0) {
        float s = 0.f;
        #pragma unroll
        for (int k = 0; k < 8; k++) s += sm[k];
        g_sumw = s;
    }
}

// ---------------------------------------------------------------- GEMM1 (f32x2)
// hidden = relu(x @ fc1_w^T + b1). M=3072,N=1024,K=256. BM=128 BN=128 BK=16.
__global__ __launch_bounds__(256) void gemm1_kernel(
    const float* __restrict__ A,
    const float* __restrict__ Bw,
    const float* __restrict__ bias)
{
    constexpr int BM = 128, BN = 128, BK = 16, K = Dc;
    __shared__ __align__(16) float As2[BK][2 * BM];   // A duplicated: [k][2m]=[k][2m+1]
    __shared__ __align__(16) float Bs[BK][BN];

    const int tid = threadIdx.x;
    const int m0 = blockIdx.y * BM, n0 = blockIdx.x * BN;
    const int ty = tid >> 4, tx = tid & 15;
    const int rm = tid >> 2;               // 0..63
    const int kq = (tid & 3) << 2;         // 0,4,8,12

    const float* Ap0 = A  + (size_t)(m0 + rm) * K + kq;
    const float* Ap1 = Ap0 + (size_t)64 * K;
    const float* Bp0 = Bw + (size_t)(n0 + rm) * K + kq;
    const float* Bp1 = Bp0 + (size_t)64 * K;

    float4 pa0 = *(const float4*)Ap0;
    float4 pa1 = *(const float4*)Ap1;
    float4 pb0 = *(const float4*)Bp0;
    float4 pb1 = *(const float4*)Bp1;

    uint64_t acc2[8][4];
    #pragma unroll
    for (int i = 0; i < 8; i++)
        #pragma unroll
        for (int j = 0; j < 4; j++) acc2[i][j] = 0ull;

    constexpr int NT = K / BK;
    for (int kt = 0; kt < NT; ++kt) {
        const float a0v[4] = {pa0.x, pa0.y, pa0.z, pa0.w};
        const float a1v[4] = {pa1.x, pa1.y, pa1.z, pa1.w};
        const float b0v[4] = {pb0.x, pb0.y, pb0.z, pb0.w};
        const float b1v[4] = {pb1.x, pb1.y, pb1.z, pb1.w};
        #pragma unroll
        for (int u = 0; u < 4; u++) {
            *(uint64_t*)&As2[kq + u][2 * rm]        = pk2(a0v[u], a0v[u]);
            *(uint64_t*)&As2[kq + u][2 * (rm + 64)] = pk2(a1v[u], a1v[u]);
            Bs[kq + u][rm]      = b0v[u];
            Bs[kq + u][rm + 64] = b1v[u];
        }
        __syncthreads();

        if (kt + 1 < NT) {
            pa0 = *(const float4*)(Ap0 + (kt + 1) * BK);
            pa1 = *(const float4*)(Ap1 + (kt + 1) * BK);
            pb0 = *(const float4*)(Bp0 + (kt + 1) * BK);
            pb1 = *(const float4*)(Bp1 + (kt + 1) * BK);
        }

        #pragma unroll
        for (int k = 0; k < BK; k++) {
            uint64_t a2[8], b2[4];
            ulonglong2 t;
            t = *(const ulonglong2*)&As2[k][ty * 16];      a2[0] = t.x; a2[1] = t.y;
            t = *(const ulonglong2*)&As2[k][ty * 16 + 4];  a2[2] = t.x; a2[3] = t.y;
            t = *(const ulonglong2*)&As2[k][ty * 16 + 8];  a2[4] = t.x; a2[5] = t.y;
            t = *(const ulonglong2*)&As2[k][ty * 16 + 12]; a2[6] = t.x; a2[7] = t.y;
            t = *(const ulonglong2*)&Bs[k][tx * 8];        b2[0] = t.x; b2[1] = t.y;
            t = *(const ulonglong2*)&Bs[k][tx * 8 + 4];    b2[2] = t.x; b2[3] = t.y;
            #pragma unroll
            for (int i = 0; i < 8; i++)
                #pragma unroll
                for (int jp = 0; jp < 4; jp++)
                    acc2[i][jp] = fma2(a2[i], b2[jp], acc2[i][jp]);
        }
        __syncthreads();
    }

    float bb[8];
    *(float4*)&bb[0] = *(const float4*)&bias[n0 + tx * 8];
    *(float4*)&bb[4] = *(const float4*)&bias[n0 + tx * 8 + 4];

    #pragma unroll
    for (int i = 0; i < 8; i++) {
        const size_t m = (size_t)(m0 + ty * 8 + i);
        float o[8];
        #pragma unroll
        for (int jp = 0; jp < 4; jp++) {
            float2 v = upk2(acc2[i][jp]);
            o[2 * jp]     = fmaxf(v.x + bb[2 * jp], 0.f);
            o[2 * jp + 1] = fmaxf(v.y + bb[2 * jp + 1], 0.f);
        }
        *(float4*)&g_hidden[m * Hc + n0 + tx * 8]     = *(float4*)&o[0];
        *(float4*)&g_hidden[m * Hc + n0 + tx * 8 + 4] = *(float4*)&o[4];
    }
}

// ---------------------------------------------------------------- GEMM2 (f32x2)
// x_hat = hidden @ fc2_w^T + b2 ; y = x_hat*w. M=3072,N=256,K=1024. BM=64 BN=64 BK=16.
__global__ __launch_bounds__(256) void gemm2_kernel(
    const float* __restrict__ Bw,
    const float* __restrict__ bias,
    const float* __restrict__ w,
    float* __restrict__ xhat)
{
    constexpr int BM = 64, BN = 64, BK = 16, K = Hc;
    __shared__ __align__(16) float As2[BK][2 * BM];
    __shared__ __align__(16) float Bs[BK][BN];

    const int tid = threadIdx.x;
    const int m0 = blockIdx.y * BM, n0 = blockIdx.x * BN;
    const int ty = tid >> 4, tx = tid & 15;
    const int rm = tid >> 2;
    const int kq = (tid & 3) << 2;

    const float* Ap = g_hidden + (size_t)(m0 + rm) * K + kq;
    const float* Bp = Bw       + (size_t)(n0 + rm) * K + kq;

    float4 pa = *(const float4*)Ap;
    float4 pb = *(const float4*)Bp;

    uint64_t acc2[4][2];
    #pragma unroll
    for (int i = 0; i < 4; i++) { acc2[i][0] = 0ull; acc2[i][1] = 0ull; }

    constexpr int NT = K / BK;
    for (int kt = 0; kt < NT; ++kt) {
        const float av[4] = {pa.x, pa.y, pa.z, pa.w};
        const float bv[4] = {pb.x, pb.y, pb.z, pb.w};
        #pragma unroll
        for (int u = 0; u < 4; u++) {
            *(uint64_t*)&As2[kq + u][2 * rm] = pk2(av[u], av[u]);
            Bs[kq + u][rm] = bv[u];
        }
        __syncthreads();

        if (kt + 1 < NT) {
            pa = *(const float4*)(Ap + (kt + 1) * BK);
            pb = *(const float4*)(Bp + (kt + 1) * BK);
        }

        #pragma unroll
        for (int k = 0; k < BK; k++) {
            uint64_t a2[4], b2[2];
            ulonglong2 t;
            t = *(const ulonglong2*)&As2[k][ty * 8];     a2[0] = t.x; a2[1] = t.y;
            t = *(const ulonglong2*)&As2[k][ty * 8 + 4]; a2[2] = t.x; a2[3] = t.y;
            t = *(const ulonglong2*)&Bs[k][tx * 4];      b2[0] = t.x; b2[1] = t.y;
            #pragma unroll
            for (int i = 0; i < 4; i++) {
                acc2[i][0] = fma2(a2[i], b2[0], acc2[i][0]);
                acc2[i][1] = fma2(a2[i], b2[1], acc2[i][1]);
            }
        }
        __syncthreads();
    }

    float bb[4], ww[4];
    *(float4*)&bb[0] = *(const float4*)&bias[n0 + tx * 4];
    *(float4*)&ww[0] = *(const float4*)&w[n0 + tx * 4];

    #pragma unroll
    for (int i = 0; i < 4; i++) {
        const size_t m = (size_t)(m0 + ty * 4 + i);
        float2 v0 = upk2(acc2[i][0]), v1 = upk2(acc2[i][1]);
        float4 o, yv;
        o.x = v0.x + bb[0]; o.y = v0.y + bb[1];
        o.z = v1.x + bb[2]; o.w = v1.y + bb[3];
        yv.x = o.x * ww[0]; yv.y = o.y * ww[1]; yv.z = o.z * ww[2]; yv.w = o.w * ww[3];
        *(float4*)&xhat[m * Dc + n0 + tx * 4] = o;
        *(float4*)&g_y [m * Dc + n0 + tx * 4] = yv;
    }
}

// ---------------------------------------------------------------- distance + masked softmax
// 384 threads: 12 warps x 2 rows x 12 col-groups. 24 rows/block, 128 blocks.
__device__ __forceinline__ void cp_async16(uint32_t dst, const void* src) {
    asm volatile("cp.async.cg.shared.global [%0], [%1], 16;\n" :: "r"(dst), "l"(src));
}

#define XJ_STR 36

__global__ __launch_bounds__(384) void dist_kernel(
    const float* __restrict__ adj,
    const int* __restrict__ box_num,
    float* __restrict__ out)
{
    extern __shared__ __align__(16) float sm[];
    float* s_xi = sm;                  // [24][256]  (NEGATED xi)
    float* s_xj = sm + 24 * Dc;        // [2][384][XJ_STR]

    const int tid = threadIdx.x;
    const int b  = blockIdx.y;
    const int i0 = blockIdx.x * 24;
    const float* yb = g_y + (size_t)b * Nc * Dc;

    // Load xi tile NEGATED: |xi - xj| == |xj + (-xi)|
    #pragma unroll
    for (int p = 0; p < 4; p++) {
        int q = tid + 384 * p;             // 0..1535
        int i = q >> 6, c4 = (q & 63) << 2;
        float4 v = *(const float4*)&yb[(size_t)(i0 + i) * Dc + c4];
        v.x = -v.x; v.y = -v.y; v.z = -v.z; v.w = -v.w;
        *(float4*)&s_xi[i * Dc + c4] = v;
    }

    const uint32_t xj_addr = (uint32_t)__cvta_generic_to_shared(s_xj);

    #pragma unroll
    for (int p = 0; p < 8; p++) {
        int id = tid + 384 * p;            // 0..3071
        int j = id >> 3, u = id & 7;
        cp_async16(xj_addr + (uint32_t)((j * XJ_STR + u * 4) << 2),
                   &yb[(size_t)j * Dc + u * 4]);
    }
    asm volatile("cp.async.commit_group;\n" ::: "memory");

    uint64_t acc2[2][12];
    #pragma unroll
    for (int r = 0; r < 2; r++)
        #pragma unroll
        for (int g = 0; g < 12; g++) acc2[r][g] = 0ull;

    const int lane = tid & 31, ty = tid >> 5;   // 12 warps
    const int ib = ty * 2;

    for (int c = 0; c < 8; c++) {
        if (c < 7) {
            uint32_t base = xj_addr + (uint32_t)(((c + 1) & 1) * (Nc * XJ_STR * 4));
            #pragma unroll
            for (int p = 0; p < 8; p++) {
                int id = tid + 384 * p;
                int j = id >> 3, u = id & 7;
                cp_async16(base + (uint32_t)((j * XJ_STR + u * 4) << 2),
                           &yb[(size_t)j * Dc + (c + 1) * 32 + u * 4]);
            }
            asm volatile("cp.async.commit_group;\n" ::: "memory");
            asm volatile("cp.async.wait_group 1;\n" ::: "memory");
        } else {
            asm volatile("cp.async.wait_group 0;\n" ::: "memory");
        }
        __syncthreads();

        const float* xjc = s_xj + (c & 1) * (Nc * XJ_STR);
        #pragma unroll
        for (int d4 = 0; d4 < 8; d4++) {
            const int dof = c * 32 + d4 * 4;
            ulonglong2 xi0 = *(const ulonglong2*)&s_xi[(ib + 0) * Dc + dof];
            ulonglong2 xi1 = *(const ulonglong2*)&s_xi[(ib + 1) * Dc + dof];
            #pragma unroll
            for (int g = 0; g < 12; g++) {
                const ulonglong2 xv = *(const ulonglong2*)&xjc[(lane + 32 * g) * XJ_STR + d4 * 4];
                uint64_t d00 = add2(xv.x, xi0.x) & ABS2;
                uint64_t d01 = add2(xv.y, xi0.y) & ABS2;
                uint64_t d10 = add2(xv.x, xi1.x) & ABS2;
                uint64_t d11 = add2(xv.y, xi1.y) & ABS2;
                acc2[0][g] = add2(acc2[0][g], d00);
                acc2[1][g] = add2(acc2[1][g], d10);
                acc2[0][g] = add2(acc2[0][g], d01);
                acc2[1][g] = add2(acc2[1][g], d11);
            }
        }
        __syncthreads();
    }

    // Epilogue
    const int bn = box_num[b];
    const float sumw = g_sumw;
    const float* adjb = adj + (size_t)b * Nc * Nc;
    float* outb = out + (size_t)b * Nc * Nc;

    #pragma unroll
    for (int r = 0; r < 2; r++) {
        const int i = i0 + ib + r;
        const bool vi = i < bn;
        float v[12];
        float mx = -3.4e38f;
        #pragma unroll
        for (int g = 0; g < 12; g++) {
            const int j = lane + 32 * g;
            float2 p = upk2(acc2[r][g]);
            float t = p.x + p.y;
            if (!(vi && (j < bn))) t -= sumw;
            t = (t >= 0.f) ? t : 0.01f * t;
            v[g] = t;
            mx = fmaxf(mx, t);
        }
        #pragma unroll
        for (int off = 16; off; off >>= 1) mx = fmaxf(mx, __shfl_xor_sync(0xffffffffu, mx, off));
        float s = 0.f;
        #pragma unroll
        for (int g = 0; g < 12; g++) {
            const int j = lane + 32 * g;
            const float e = adjb[(size_t)i * Nc + j] * __expf(v[g] - mx);
            v[g] = e; s += e;
        }
        #pragma unroll
        for (int off = 16; off; off >>= 1) s += __shfl_xor_sync(0xffffffffu, s, off);
        const float inv = 1.f / s;
        #pragma unroll
        for (int g = 0; g < 12; g++) {
            const int j = lane + 32 * g;
            outb[(size_t)i * Nc + j] = v[g] * inv + 1e-10f;
        }
    }
}

// ---------------------------------------------------------------- launch
extern "C" void kernel_launch(void* const* d_in, const int* in_sizes, int n_in,
                              void* d_out, int out_size)
{
    const float* x       = (const float*)d_in[0];
    const float* adj     = (const float*)d_in[1];
    const int*   box_num = (const int*)d_in[2];
    const float* fc1_w   = (const float*)d_in[3];
    const float* fc1_b   = (const float*)d_in[4];
    const float* fc2_w   = (const float*)d_in[5];
    const float* fc2_b   = (const float*)d_in[6];
    const float* learn_w = (const float*)d_in[7];

    float* soft = (float*)d_out;                        // [8,384,384]
    float* xhat = soft + (size_t)Bc * Nc * Nc;          // [8,384,256]

    sumw_kernel<<<1, 256>>>(learn_w);
    gemm1_kernel<<<dim3(Hc / 128, MR / 128), 256>>>(x, fc1_w, fc1_b);
    gemm2_kernel<<<dim3(Dc / 64, MR / 64), 256>>>(fc2_w, fc2_b, learn_w, xhat);

    const int shm = (24 * Dc + 2 * Nc * XJ_STR) * 4;    // 135168 B
    cudaFuncSetAttribute(dist_kernel, cudaFuncAttributeMaxDynamicSharedMemorySize, shm);
    dist_kernel<<<dim3(Nc / 24, Bc), 384, shm>>>(adj, box_num, soft);
}

// round 5
// speedup vs baseline: 2.1139x; 2.1139x over previous
#include <cuda_runtime.h>
#include <cuda_bf16.h>
#include <cstdint>
#include <cstddef>

#define Bc 8
#define Nc 384
#define Dc 256
#define Hc 1024
#define MR (Bc*Nc)   // 3072

// ----------------------------------------------------------------- scratch
__device__ __align__(128) float g_y[(size_t)MR * Dc];
__device__ float g_sumw;
__device__ __align__(128) __nv_bfloat16 g_xhi[(size_t)MR * Dc],  g_xlo[(size_t)MR * Dc];
__device__ __align__(128) __nv_bfloat16 g_w1hi[(size_t)Hc * Dc], g_w1lo[(size_t)Hc * Dc];
__device__ __align__(128) __nv_bfloat16 g_w2hi[(size_t)Dc * Hc], g_w2lo[(size_t)Dc * Hc];
__device__ __align__(128) __nv_bfloat16 g_hhi[(size_t)MR * Hc],  g_hlo[(size_t)MR * Hc];

// ----------------------------------------------------------------- helpers
__device__ __forceinline__ uint32_t smem_u32(const void* p) {
    uint32_t a;
    asm("{ .reg .u64 t; cvta.to.shared.u64 t, %1; cvt.u32.u64 %0, t; }" : "=r"(a) : "l"(p));
    return a;
}
__device__ __forceinline__ void cp_async16(uint32_t dst, const void* src) {
    asm volatile("cp.async.cg.shared.global [%0], [%1], 16;\n" :: "r"(dst), "l"(src));
}
#define CP_COMMIT()  asm volatile("cp.async.commit_group;\n" ::: "memory")
#define CP_WAIT0()   asm volatile("cp.async.wait_group 0;\n" ::: "memory")
#define CP_WAIT1()   asm volatile("cp.async.wait_group 1;\n" ::: "memory")

__device__ __forceinline__ void ldsm_x4(uint32_t* r, uint32_t addr) {
    asm volatile("ldmatrix.sync.aligned.m8n8.x4.shared.b16 {%0,%1,%2,%3}, [%4];"
        : "=r"(r[0]), "=r"(r[1]), "=r"(r[2]), "=r"(r[3]) : "r"(addr));
}
__device__ __forceinline__ void mma_bf16(float* c, const uint32_t* a, const uint32_t* b) {
    asm volatile(
        "mma.sync.aligned.m16n8k16.row.col.f32.bf16.bf16.f32 "
        "{%0,%1,%2,%3}, {%4,%5,%6,%7}, {%8,%9}, {%0,%1,%2,%3};"
        : "+f"(c[0]), "+f"(c[1]), "+f"(c[2]), "+f"(c[3])
        : "r"(a[0]), "r"(a[1]), "r"(a[2]), "r"(a[3]), "r"(b[0]), "r"(b[1]));
}
__device__ __forceinline__ uint32_t cvt_bf16x2(float hi, float lo) {
    uint32_t r; asm("cvt.rn.bf16x2.f32 %0, %1, %2;" : "=r"(r) : "f"(hi), "f"(lo)); return r;
}

// ----------------------------------------------------------------- misc kernels
__global__ void sumw_kernel(const float* __restrict__ w) {
    __shared__ float sm[8];
    int t = threadIdx.x;
    float v = w[t];
    #pragma unroll
    for (int off = 16; off; off >>= 1) v += __shfl_xor_sync(0xffffffffu, v, off);
    if ((t & 31) == 0) sm[t >> 5] = v;
    __syncthreads();
    if (t == 0) {
        float s = 0.f;
        #pragma unroll
        for (int k = 0; k < 8; k++) s += sm[k];
        g_sumw = s;
    }
}

__global__ void split_kernel(const float* __restrict__ src,
                             __nv_bfloat16* __restrict__ hi,
                             __nv_bfloat16* __restrict__ lo, int n) {
    for (int i = blockIdx.x * blockDim.x + threadIdx.x; i < n; i += gridDim.x * blockDim.x) {
        float v = src[i];
        __nv_bfloat16 h = __float2bfloat16(v);
        hi[i] = h;
        lo[i] = __float2bfloat16(v - __bfloat162float(h));
    }
}

// ----------------------------------------------------------------- mma.sync GEMM
// C[M,N] = A[M,K] @ B[N,K]^T with 3-term bf16 hi/lo split, fp32 accum.
// Tiles: bf16, 32 k-cols per chunk, row pitch 40 bf16 (80B) - conflict-free ldmatrix.
// EPI=1: relu -> write hidden hi/lo bf16.  EPI=2: write xhat fp32 + y=xhat*w.
template<int BM, int BN, int NW, int WMF, int K, int EPI>
__global__ void __launch_bounds__(NW * 32) mma_gemm(
    const __nv_bfloat16* __restrict__ Ahi, const __nv_bfloat16* __restrict__ Alo,
    const __nv_bfloat16* __restrict__ Bhi, const __nv_bfloat16* __restrict__ Blo,
    const float* __restrict__ bias, const float* __restrict__ wvec,
    float* __restrict__ out)
{
    constexpr int NT  = NW * 32;
    constexpr int WN  = BN / (NW / WMF);     // warp n-extent
    constexpr int NN  = WN / 8;              // n8 frags per warp
    constexpr int TA  = BM * 80;             // bytes per A tile (hi or lo)
    constexpr int TB  = BN * 80;
    constexpr int BUF = 2 * TA + 2 * TB;
    constexpr int NCH = K / 32;
    constexpr int OUTD = (EPI == 1) ? Hc : Dc;

    extern __shared__ __align__(1024) char smem[];
    float* s_bias = (float*)smem;
    float* s_w    = (float*)(smem + BN * 4);
    const uint32_t tiles = smem_u32(smem) + 1024;

    const int tid  = threadIdx.x;
    const int wid  = tid >> 5, lane = tid & 31;
    const int m0   = blockIdx.y * BM, n0 = blockIdx.x * BN;
    const int wm   = (wid % WMF) * 32;
    const int wn   = (wid / WMF) * WN;

    if (tid < BN) {
        s_bias[tid] = bias[n0 + tid];
        if (EPI == 2) s_w[tid] = wvec[n0 + tid];
    }

    float cacc[2][NN][4];
    #pragma unroll
    for (int f = 0; f < 2; f++)
        #pragma unroll
        for (int g = 0; g < NN; g++)
            #pragma unroll
            for (int e = 0; e < 4; e++) cacc[f][g][e] = 0.f;

    auto issue = [&](int c) {
        const uint32_t tb = tiles + (c & 1) * BUF;
        const int kc = c * 32;
        #pragma unroll
        for (int q = 0; q < (BM * 8) / NT; ++q) {
            const int id = q * NT + tid;
            const int mat = id / (BM * 4), e = id % (BM * 4);
            const int r = e >> 2, c16 = e & 3;
            const __nv_bfloat16* src = (mat ? Alo : Ahi) + (size_t)(m0 + r) * K + kc + c16 * 8;
            cp_async16(tb + mat * TA + r * 80 + c16 * 16, src);
        }
        #pragma unroll
        for (int q = 0; q < (BN * 8) / NT; ++q) {
            const int id = q * NT + tid;
            const int mat = id / (BN * 4), e = id % (BN * 4);
            const int r = e >> 2, c16 = e & 3;
            const __nv_bfloat16* src = (mat ? Blo : Bhi) + (size_t)(n0 + r) * K + kc + c16 * 8;
            cp_async16(tb + 2 * TA + mat * TB + r * 80 + c16 * 16, src);
        }
        CP_COMMIT();
    };

    issue(0);
    issue(1);

    for (int c = 0; c < NCH; ++c) {
        if (c + 1 < NCH) { CP_WAIT1(); } else { CP_WAIT0(); }
        __syncthreads();

        const uint32_t aBase = tiles + (c & 1) * BUF;
        const uint32_t bBase = aBase + 2 * TA;

        #pragma unroll
        for (int s = 0; s < 2; ++s) {
            const int kk = s * 16;
            uint32_t aH[2][4], aL[2][4];
            #pragma unroll
            for (int f = 0; f < 2; ++f) {
                const int row = wm + f * 16 + (lane & 15);
                const int col = kk + ((lane >> 4) << 3);
                const uint32_t ad = aBase + row * 80 + col * 2;
                ldsm_x4(aH[f], ad);
                ldsm_x4(aL[f], ad + TA);
            }
            #pragma unroll
            for (int np = 0; np < NN / 2; ++np) {
                const int rowB = wn + np * 16 + (lane & 7) + ((lane & 16) >> 1);
                const int colB = kk + (lane & 8);
                const uint32_t bd = bBase + rowB * 80 + colB * 2;
                uint32_t bH[4], bL[4];
                ldsm_x4(bH, bd);
                ldsm_x4(bL, bd + TB);
                #pragma unroll
                for (int f = 0; f < 2; ++f) {
                    #pragma unroll
                    for (int h = 0; h < 2; ++h) {
                        float* cc = cacc[f][2 * np + h];
                        mma_bf16(cc, aH[f], bH + 2 * h);
                        mma_bf16(cc, aH[f], bL + 2 * h);
                        mma_bf16(cc, aL[f], bH + 2 * h);
                    }
                }
            }
        }
        __syncthreads();
        if (c + 2 < NCH) issue(c + 2);
    }

    // ------------------------------------------------------------- epilogue
    const int tq = lane >> 2, tr = lane & 3;
    #pragma unroll
    for (int f = 0; f < 2; ++f) {
        #pragma unroll
        for (int g = 0; g < NN; ++g) {
            const int col  = n0 + wn + g * 8 + tr * 2;
            const int bcol = wn + g * 8 + tr * 2;
            #pragma unroll
            for (int half = 0; half < 2; ++half) {
                const int row = m0 + wm + f * 16 + tq + half * 8;
                float v0 = cacc[f][g][2 * half]     + s_bias[bcol];
                float v1 = cacc[f][g][2 * half + 1] + s_bias[bcol + 1];
                if (EPI == 1) {
                    v0 = fmaxf(v0, 0.f); v1 = fmaxf(v1, 0.f);
                    const uint32_t h = cvt_bf16x2(v1, v0);
                    const float h0 = __uint_as_float(h << 16);
                    const float h1 = __uint_as_float(h & 0xffff0000u);
                    const uint32_t l = cvt_bf16x2(v1 - h1, v0 - h0);
                    *(uint32_t*)&g_hhi[(size_t)row * OUTD + col] = h;
                    *(uint32_t*)&g_hlo[(size_t)row * OUTD + col] = l;
                } else {
                    float2 o; o.x = v0; o.y = v1;
                    float2 yv; yv.x = v0 * s_w[bcol]; yv.y = v1 * s_w[bcol + 1];
                    *(float2*)&out[(size_t)row * OUTD + col] = o;
                    *(float2*)&g_y[(size_t)row * OUTD + col] = yv;
                }
            }
        }
    }
}

// ----------------------------------------------------------------- dist (R2 proven)
#define XJ_STR 36

__global__ __launch_bounds__(256) void dist_kernel(
    const float* __restrict__ adj,
    const int* __restrict__ box_num,
    float* __restrict__ out)
{
    extern __shared__ __align__(16) float sm[];
    float* s_xi = sm;                  // [24][256]
    float* s_xj = sm + 24 * Dc;        // [2][384][XJ_STR]

    const int tid = threadIdx.x;
    const int b  = blockIdx.y;
    const int i0 = blockIdx.x * 24;
    const float* yb = g_y + (size_t)b * Nc * Dc;

    #pragma unroll
    for (int p = 0; p < 6; p++) {
        int q = tid + 256 * p;
        int i = q >> 6, c4 = (q & 63) << 2;
        *(float4*)&s_xi[i * Dc + c4] = *(const float4*)&yb[(size_t)(i0 + i) * Dc + c4];
    }

    const uint32_t xj_addr = smem_u32(s_xj);

    #pragma unroll
    for (int p = 0; p < 12; p++) {
        int id = tid + 256 * p;
        int j = id >> 3, u = id & 7;
        cp_async16(xj_addr + (uint32_t)((j * XJ_STR + u * 4) << 2),
                   &yb[(size_t)j * Dc + u * 4]);
    }
    CP_COMMIT();

    float acc[3][12];
    #pragma unroll
    for (int r = 0; r < 3; r++)
        #pragma unroll
        for (int g = 0; g < 12; g++) acc[r][g] = 0.f;

    const int lane = tid & 31, ty = tid >> 5;
    const int ib = ty * 3;

    for (int c = 0; c < 8; c++) {
        if (c < 7) {
            uint32_t base = xj_addr + (uint32_t)(((c + 1) & 1) * (Nc * XJ_STR * 4));
            #pragma unroll
            for (int p = 0; p < 12; p++) {
                int id = tid + 256 * p;
                int j = id >> 3, u = id & 7;
                cp_async16(base + (uint32_t)((j * XJ_STR + u * 4) << 2),
                           &yb[(size_t)j * Dc + (c + 1) * 32 + u * 4]);
            }
            CP_COMMIT();
            CP_WAIT1();
        } else {
            CP_WAIT0();
        }
        __syncthreads();

        const float* xjc = s_xj + (c & 1) * (Nc * XJ_STR);
        #pragma unroll
        for (int d4 = 0; d4 < 8; d4++) {
            const int dof = c * 32 + d4 * 4;
            const float4 x0 = *(const float4*)&s_xi[(ib + 0) * Dc + dof];
            const float4 x1 = *(const float4*)&s_xi[(ib + 1) * Dc + dof];
            const float4 x2 = *(const float4*)&s_xi[(ib + 2) * Dc + dof];
            #pragma unroll
            for (int g = 0; g < 12; g++) {
                const float4 xv = *(const float4*)&xjc[(lane + 32 * g) * XJ_STR + d4 * 4];
                float a0 = acc[0][g], a1 = acc[1][g], a2 = acc[2][g];
                a0 += fabsf(x0.x - xv.x); a0 += fabsf(x0.y - xv.y);
                a0 += fabsf(x0.z - xv.z); a0 += fabsf(x0.w - xv.w);
                a1 += fabsf(x1.x - xv.x); a1 += fabsf(x1.y - xv.y);
                a1 += fabsf(x1.z - xv.z); a1 += fabsf(x1.w - xv.w);
                a2 += fabsf(x2.x - xv.x); a2 += fabsf(x2.y - xv.y);
                a2 += fabsf(x2.z - xv.z); a2 += fabsf(x2.w - xv.w);
                acc[0][g] = a0; acc[1][g] = a1; acc[2][g] = a2;
            }
        }
        __syncthreads();
    }

    const int bn = box_num[b];
    const float sumw = g_sumw;
    const float* adjb = adj + (size_t)b * Nc * Nc;
    float* outb = out + (size_t)b * Nc * Nc;

    #pragma unroll
    for (int r = 0; r < 3; r++) {
        const int i = i0 + ib + r;
        const bool vi = i < bn;
        float v[12];
        float mx = -3.4e38f;
        #pragma unroll
        for (int g = 0; g < 12; g++) {
            const int j = lane + 32 * g;
            float t = acc[r][g];
            if (!(vi && (j < bn))) t -= sumw;
            t = (t >= 0.f) ? t : 0.01f * t;
            v[g] = t;
            mx = fmaxf(mx, t);
        }
        #pragma unroll
        for (int off = 16; off; off >>= 1) mx = fmaxf(mx, __shfl_xor_sync(0xffffffffu, mx, off));
        float s = 0.f;
        #pragma unroll
        for (int g = 0; g < 12; g++) {
            const int j = lane + 32 * g;
            const float e = adjb[(size_t)i * Nc + j] * __expf(v[g] - mx);
            v[g] = e; s += e;
        }
        #pragma unroll
        for (int off = 16; off; off >>= 1) s += __shfl_xor_sync(0xffffffffu, s, off);
        const float inv = 1.f / s;
        #pragma unroll
        for (int g = 0; g < 12; g++) {
            const int j = lane + 32 * g;
            outb[(size_t)i * Nc + j] = v[g] * inv + 1e-10f;
        }
    }
}

// ----------------------------------------------------------------- launch
// GEMM1: 128x128 CTA, 8 warps (4x2), K=256  -> grid (8,24)=192
// GEMM2: 64x64 CTA, 4 warps (2x2), K=1024   -> grid (4,48)=192
#define SMEM1 (1024 + 2 * (2 * 128 * 80 + 2 * 128 * 80))   // 82944
#define SMEM2 (1024 + 2 * (2 * 64 * 80 + 2 * 64 * 80))     // 41984

extern "C" void kernel_launch(void* const* d_in, const int* in_sizes, int n_in,
                              void* d_out, int out_size)
{
    const float* x       = (const float*)d_in[0];
    const float* adj     = (const float*)d_in[1];
    const int*   box_num = (const int*)d_in[2];
    const float* fc1_w   = (const float*)d_in[3];
    const float* fc1_b   = (const float*)d_in[4];
    const float* fc2_w   = (const float*)d_in[5];
    const float* fc2_b   = (const float*)d_in[6];
    const float* learn_w = (const float*)d_in[7];

    float* soft = (float*)d_out;                   // [8,384,384]
    float* xhat = soft + (size_t)Bc * Nc * Nc;     // [8,384,256]

    static __nv_bfloat16 *xhi, *xlo, *w1hi, *w1lo, *w2hi, *w2lo, *hhi, *hlo;
    static bool init = false;
    if (!init) {
        cudaGetSymbolAddress((void**)&xhi,  g_xhi);
        cudaGetSymbolAddress((void**)&xlo,  g_xlo);
        cudaGetSymbolAddress((void**)&w1hi, g_w1hi);
        cudaGetSymbolAddress((void**)&w1lo, g_w1lo);
        cudaGetSymbolAddress((void**)&w2hi, g_w2hi);
        cudaGetSymbolAddress((void**)&w2lo, g_w2lo);
        cudaGetSymbolAddress((void**)&hhi,  g_hhi);
        cudaGetSymbolAddress((void**)&hlo,  g_hlo);
        cudaFuncSetAttribute((const void*)mma_gemm<128,128,8,4,Dc,1>,
                             cudaFuncAttributeMaxDynamicSharedMemorySize, SMEM1);
        cudaFuncSetAttribute((const void*)mma_gemm<64,64,4,2,Hc,2>,
                             cudaFuncAttributeMaxDynamicSharedMemorySize, SMEM2);
        cudaFuncSetAttribute((const void*)dist_kernel,
                             cudaFuncAttributeMaxDynamicSharedMemorySize,
                             (24 * Dc + 2 * Nc * XJ_STR) * 4);
        init = true;
    }

    sumw_kernel<<<1, 256>>>(learn_w);
    split_kernel<<<592, 256>>>(x, xhi, xlo, MR * Dc);
    split_kernel<<<296, 256>>>(fc1_w, w1hi, w1lo, Hc * Dc);
    split_kernel<<<296, 256>>>(fc2_w, w2hi, w2lo, Dc * Hc);

    mma_gemm<128,128,8,4,Dc,1><<<dim3(Hc/128, MR/128), 256, SMEM1>>>(
        xhi, xlo, w1hi, w1lo, fc1_b, nullptr, nullptr);
    mma_gemm<64,64,4,2,Hc,2><<<dim3(Dc/64, MR/64), 128, SMEM2>>>(
        hhi, hlo, w2hi, w2lo, fc2_b, learn_w, xhat);

    const int shm = (24 * Dc + 2 * Nc * XJ_STR) * 4;
    dist_kernel<<<dim3(Nc / 24, Bc), 256, shm>>>(adj, box_num, soft);
}

// round 6
// speedup vs baseline: 2.2507x; 1.0647x over previous
#include <cuda_runtime.h>
#include <cuda_bf16.h>
#include <cstdint>
#include <cstddef>

#define Bc 8
#define Nc 384
#define Dc 256
#define Hc 1024
#define MR (Bc*Nc)   // 3072

// ----------------------------------------------------------------- scratch
__device__ __align__(128) float g_y[(size_t)MR * Dc];
__device__ float g_sumw;
__device__ __align__(128) __nv_bfloat16 g_xhi[(size_t)MR * Dc],  g_xlo[(size_t)MR * Dc];
__device__ __align__(128) __nv_bfloat16 g_w1hi[(size_t)Hc * Dc], g_w1lo[(size_t)Hc * Dc];
__device__ __align__(128) __nv_bfloat16 g_w2hi[(size_t)Dc * Hc], g_w2lo[(size_t)Dc * Hc];
__device__ __align__(128) __nv_bfloat16 g_hhi[(size_t)MR * Hc],  g_hlo[(size_t)MR * Hc];

// ----------------------------------------------------------------- helpers
__device__ __forceinline__ uint32_t smem_u32(const void* p) {
    uint32_t a;
    asm("{ .reg .u64 t; cvta.to.shared.u64 t, %1; cvt.u32.u64 %0, t; }" : "=r"(a) : "l"(p));
    return a;
}
__device__ __forceinline__ void cp_async16(uint32_t dst, const void* src) {
    asm volatile("cp.async.cg.shared.global [%0], [%1], 16;\n" :: "r"(dst), "l"(src));
}
#define CP_COMMIT()  asm volatile("cp.async.commit_group;\n" ::: "memory")
#define CP_WAIT0()   asm volatile("cp.async.wait_group 0;\n" ::: "memory")
#define CP_WAIT1()   asm volatile("cp.async.wait_group 1;\n" ::: "memory")

__device__ __forceinline__ void ldsm_x4(uint32_t* r, uint32_t addr) {
    asm volatile("ldmatrix.sync.aligned.m8n8.x4.shared.b16 {%0,%1,%2,%3}, [%4];"
        : "=r"(r[0]), "=r"(r[1]), "=r"(r[2]), "=r"(r[3]) : "r"(addr));
}
__device__ __forceinline__ void mma_bf16(float* c, const uint32_t* a, const uint32_t* b) {
    asm volatile(
        "mma.sync.aligned.m16n8k16.row.col.f32.bf16.bf16.f32 "
        "{%0,%1,%2,%3}, {%4,%5,%6,%7}, {%8,%9}, {%0,%1,%2,%3};"
        : "+f"(c[0]), "+f"(c[1]), "+f"(c[2]), "+f"(c[3])
        : "r"(a[0]), "r"(a[1]), "r"(a[2]), "r"(a[3]), "r"(b[0]), "r"(b[1]));
}
__device__ __forceinline__ uint32_t cvt_bf16x2(float hi, float lo) {
    uint32_t r; asm("cvt.rn.bf16x2.f32 %0, %1, %2;" : "=r"(r) : "f"(hi), "f"(lo)); return r;
}

// ----------------------------------------------------------------- fused prep
// One kernel: splits x, fc1_w, fc2_w into bf16 hi/lo AND computes sum(learn_w).
// 640 blocks x 512 threads, one float4 per thread (327680 total float4s).
#define N4X ((MR * Dc) / 4)      // 196608
#define N4W ((Hc * Dc) / 4)      // 65536
#define N4TOT (N4X + 2 * N4W)    // 327680

__global__ __launch_bounds__(512) void prep_kernel(
    const float* __restrict__ x, const float* __restrict__ w1,
    const float* __restrict__ w2, const float* __restrict__ lw)
{
    const int gid = blockIdx.x * 512 + threadIdx.x;

    const float* src;
    __nv_bfloat16 *hi, *lo;
    int idx;
    if (gid < N4X)            { src = x;  hi = g_xhi;  lo = g_xlo;  idx = gid; }
    else if (gid < N4X + N4W) { src = w1; hi = g_w1hi; lo = g_w1lo; idx = gid - N4X; }
    else                      { src = w2; hi = g_w2hi; lo = g_w2lo; idx = gid - N4X - N4W; }

    const float4 v = *(const float4*)(src + 4 * (size_t)idx);
    uint2 hw, lw4;
    hw.x = cvt_bf16x2(v.y, v.x);
    hw.y = cvt_bf16x2(v.w, v.z);
    {
        const float h0 = __uint_as_float(hw.x << 16);
        const float h1 = __uint_as_float(hw.x & 0xffff0000u);
        const float h2 = __uint_as_float(hw.y << 16);
        const float h3 = __uint_as_float(hw.y & 0xffff0000u);
        lw4.x = cvt_bf16x2(v.y - h1, v.x - h0);
        lw4.y = cvt_bf16x2(v.w - h3, v.z - h2);
    }
    *(uint2*)(hi + 4 * (size_t)idx) = hw;
    *(uint2*)(lo + 4 * (size_t)idx) = lw4;

    // block 0, first 256 threads: sum(learn_w)
    if (blockIdx.x == 0 && threadIdx.x < 256) {
        __shared__ float sm[8];
        const int t = threadIdx.x;
        float s = lw[t];
        #pragma unroll
        for (int off = 16; off; off >>= 1) s += __shfl_xor_sync(0xffffffffu, s, off);
        if ((t & 31) == 0) sm[t >> 5] = s;
        __syncthreads();
        if (t == 0) {
            float acc = 0.f;
            #pragma unroll
            for (int k = 0; k < 8; k++) acc += sm[k];
            g_sumw = acc;
        }
    }
}

// ----------------------------------------------------------------- mma.sync GEMM
// C[M,N] = A[M,K] @ B[N,K]^T with 3-term bf16 hi/lo split, fp32 accum.
// Tiles: bf16, 32 k-cols per chunk, row pitch 40 bf16 (80B) - conflict-free ldmatrix.
// EPI=1: relu -> write hidden hi/lo bf16.  EPI=2: write xhat fp32 + y=xhat*w.
template<int BM, int BN, int NW, int WMF, int K, int EPI>
__global__ void __launch_bounds__(NW * 32) mma_gemm(
    const __nv_bfloat16* __restrict__ Ahi, const __nv_bfloat16* __restrict__ Alo,
    const __nv_bfloat16* __restrict__ Bhi, const __nv_bfloat16* __restrict__ Blo,
    const float* __restrict__ bias, const float* __restrict__ wvec,
    float* __restrict__ out)
{
    constexpr int NT  = NW * 32;
    constexpr int WN  = BN / (NW / WMF);     // warp n-extent
    constexpr int NN  = WN / 8;              // n8 frags per warp
    constexpr int TA  = BM * 80;             // bytes per A tile (hi or lo)
    constexpr int TB  = BN * 80;
    constexpr int BUF = 2 * TA + 2 * TB;
    constexpr int NCH = K / 32;
    constexpr int OUTD = (EPI == 1) ? Hc : Dc;

    extern __shared__ __align__(1024) char smem[];
    float* s_bias = (float*)smem;
    float* s_w    = (float*)(smem + BN * 4);
    const uint32_t tiles = smem_u32(smem) + 1024;

    const int tid  = threadIdx.x;
    const int wid  = tid >> 5, lane = tid & 31;
    const int m0   = blockIdx.y * BM, n0 = blockIdx.x * BN;
    const int wm   = (wid % WMF) * 32;
    const int wn   = (wid / WMF) * WN;

    if (tid < BN) {
        s_bias[tid] = bias[n0 + tid];
        if (EPI == 2) s_w[tid] = wvec[n0 + tid];
    }

    float cacc[2][NN][4];
    #pragma unroll
    for (int f = 0; f < 2; f++)
        #pragma unroll
        for (int g = 0; g < NN; g++)
            #pragma unroll
            for (int e = 0; e < 4; e++) cacc[f][g][e] = 0.f;

    auto issue = [&](int c) {
        const uint32_t tb = tiles + (c & 1) * BUF;
        const int kc = c * 32;
        #pragma unroll
        for (int q = 0; q < (BM * 8) / NT; ++q) {
            const int id = q * NT + tid;
            const int mat = id / (BM * 4), e = id % (BM * 4);
            const int r = e >> 2, c16 = e & 3;
            const __nv_bfloat16* src = (mat ? Alo : Ahi) + (size_t)(m0 + r) * K + kc + c16 * 8;
            cp_async16(tb + mat * TA + r * 80 + c16 * 16, src);
        }
        #pragma unroll
        for (int q = 0; q < (BN * 8) / NT; ++q) {
            const int id = q * NT + tid;
            const int mat = id / (BN * 4), e = id % (BN * 4);
            const int r = e >> 2, c16 = e & 3;
            const __nv_bfloat16* src = (mat ? Blo : Bhi) + (size_t)(n0 + r) * K + kc + c16 * 8;
            cp_async16(tb + 2 * TA + mat * TB + r * 80 + c16 * 16, src);
        }
        CP_COMMIT();
    };

    issue(0);
    issue(1);

    for (int c = 0; c < NCH; ++c) {
        if (c + 1 < NCH) { CP_WAIT1(); } else { CP_WAIT0(); }
        __syncthreads();

        const uint32_t aBase = tiles + (c & 1) * BUF;
        const uint32_t bBase = aBase + 2 * TA;

        #pragma unroll
        for (int s = 0; s < 2; ++s) {
            const int kk = s * 16;
            uint32_t aH[2][4], aL[2][4];
            #pragma unroll
            for (int f = 0; f < 2; ++f) {
                const int row = wm + f * 16 + (lane & 15);
                const int col = kk + ((lane >> 4) << 3);
                const uint32_t ad = aBase + row * 80 + col * 2;
                ldsm_x4(aH[f], ad);
                ldsm_x4(aL[f], ad + TA);
            }
            #pragma unroll
            for (int np = 0; np < NN / 2; ++np) {
                const int rowB = wn + np * 16 + (lane & 7) + ((lane & 16) >> 1);
                const int colB = kk + (lane & 8);
                const uint32_t bd = bBase + rowB * 80 + colB * 2;
                uint32_t bH[4], bL[4];
                ldsm_x4(bH, bd);
                ldsm_x4(bL, bd + TB);
                #pragma unroll
                for (int f = 0; f < 2; ++f) {
                    #pragma unroll
                    for (int h = 0; h < 2; ++h) {
                        float* cc = cacc[f][2 * np + h];
                        mma_bf16(cc, aH[f], bH + 2 * h);
                        mma_bf16(cc, aH[f], bL + 2 * h);
                        mma_bf16(cc, aL[f], bH + 2 * h);
                    }
                }
            }
        }
        __syncthreads();
        if (c + 2 < NCH) issue(c + 2);
    }

    // ------------------------------------------------------------- epilogue
    const int tq = lane >> 2, tr = lane & 3;
    #pragma unroll
    for (int f = 0; f < 2; ++f) {
        #pragma unroll
        for (int g = 0; g < NN; ++g) {
            const int col  = n0 + wn + g * 8 + tr * 2;
            const int bcol = wn + g * 8 + tr * 2;
            #pragma unroll
            for (int half = 0; half < 2; ++half) {
                const int row = m0 + wm + f * 16 + tq + half * 8;
                float v0 = cacc[f][g][2 * half]     + s_bias[bcol];
                float v1 = cacc[f][g][2 * half + 1] + s_bias[bcol + 1];
                if (EPI == 1) {
                    v0 = fmaxf(v0, 0.f); v1 = fmaxf(v1, 0.f);
                    const uint32_t h = cvt_bf16x2(v1, v0);
                    const float h0 = __uint_as_float(h << 16);
                    const float h1 = __uint_as_float(h & 0xffff0000u);
                    const uint32_t l = cvt_bf16x2(v1 - h1, v0 - h0);
                    *(uint32_t*)&g_hhi[(size_t)row * OUTD + col] = h;
                    *(uint32_t*)&g_hlo[(size_t)row * OUTD + col] = l;
                } else {
                    float2 o; o.x = v0; o.y = v1;
                    float2 yv; yv.x = v0 * s_w[bcol]; yv.y = v1 * s_w[bcol + 1];
                    *(float2*)&out[(size_t)row * OUTD + col] = o;
                    *(float2*)&g_y[(size_t)row * OUTD + col] = yv;
                }
            }
        }
    }
}

// ----------------------------------------------------------------- dist
// 384 threads: 12 warps x 2 rows x 12 col-groups. 24 rows/block, 128 blocks.
#define XJ_STR 36

__global__ __launch_bounds__(384) void dist_kernel(
    const float* __restrict__ adj,
    const int* __restrict__ box_num,
    float* __restrict__ out)
{
    extern __shared__ __align__(16) float sm[];
    float* s_xi = sm;                  // [24][256]
    float* s_xj = sm + 24 * Dc;        // [2][384][XJ_STR]

    const int tid = threadIdx.x;
    const int b  = blockIdx.y;
    const int i0 = blockIdx.x * 24;
    const float* yb = g_y + (size_t)b * Nc * Dc;

    #pragma unroll
    for (int p = 0; p < 4; p++) {
        int q = tid + 384 * p;             // 0..1535
        int i = q >> 6, c4 = (q & 63) << 2;
        *(float4*)&s_xi[i * Dc + c4] = *(const float4*)&yb[(size_t)(i0 + i) * Dc + c4];
    }

    const uint32_t xj_addr = smem_u32(s_xj);

    #pragma unroll
    for (int p = 0; p < 8; p++) {
        int id = tid + 384 * p;            // 0..3071
        int j = id >> 3, u = id & 7;
        cp_async16(xj_addr + (uint32_t)((j * XJ_STR + u * 4) << 2),
                   &yb[(size_t)j * Dc + u * 4]);
    }
    CP_COMMIT();

    float acc[2][12];
    #pragma unroll
    for (int r = 0; r < 2; r++)
        #pragma unroll
        for (int g = 0; g < 12; g++) acc[r][g] = 0.f;

    const int lane = tid & 31, ty = tid >> 5;   // 12 warps
    const int ib = ty * 2;

    for (int c = 0; c < 8; c++) {
        if (c < 7) {
            uint32_t base = xj_addr + (uint32_t)(((c + 1) & 1) * (Nc * XJ_STR * 4));
            #pragma unroll
            for (int p = 0; p < 8; p++) {
                int id = tid + 384 * p;
                int j = id >> 3, u = id & 7;
                cp_async16(base + (uint32_t)((j * XJ_STR + u * 4) << 2),
                           &yb[(size_t)j * Dc + (c + 1) * 32 + u * 4]);
            }
            CP_COMMIT();
            CP_WAIT1();
        } else {
            CP_WAIT0();
        }
        __syncthreads();

        const float* xjc = s_xj + (c & 1) * (Nc * XJ_STR);
        #pragma unroll
        for (int d4 = 0; d4 < 8; d4++) {
            const int dof = c * 32 + d4 * 4;
            const float4 x0 = *(const float4*)&s_xi[(ib + 0) * Dc + dof];
            const float4 x1 = *(const float4*)&s_xi[(ib + 1) * Dc + dof];
            #pragma unroll
            for (int g = 0; g < 12; g++) {
                const float4 xv = *(const float4*)&xjc[(lane + 32 * g) * XJ_STR + d4 * 4];
                float a0 = acc[0][g], a1 = acc[1][g];
                a0 += fabsf(x0.x - xv.x); a0 += fabsf(x0.y - xv.y);
                a0 += fabsf(x0.z - xv.z); a0 += fabsf(x0.w - xv.w);
                a1 += fabsf(x1.x - xv.x); a1 += fabsf(x1.y - xv.y);
                a1 += fabsf(x1.z - xv.z); a1 += fabsf(x1.w - xv.w);
                acc[0][g] = a0; acc[1][g] = a1;
            }
        }
        __syncthreads();
    }

    const int bn = box_num[b];
    const float sumw = g_sumw;
    const float* adjb = adj + (size_t)b * Nc * Nc;
    float* outb = out + (size_t)b * Nc * Nc;

    #pragma unroll
    for (int r = 0; r < 2; r++) {
        const int i = i0 + ib + r;
        const bool vi = i < bn;
        float v[12];
        float mx = -3.4e38f;
        #pragma unroll
        for (int g = 0; g < 12; g++) {
            const int j = lane + 32 * g;
            float t = acc[r][g];
            if (!(vi && (j < bn))) t -= sumw;
            t = (t >= 0.f) ? t : 0.01f * t;
            v[g] = t;
            mx = fmaxf(mx, t);
        }
        #pragma unroll
        for (int off = 16; off; off >>= 1) mx = fmaxf(mx, __shfl_xor_sync(0xffffffffu, mx, off));
        float s = 0.f;
        #pragma unroll
        for (int g = 0; g < 12; g++) {
            const int j = lane + 32 * g;
            const float e = adjb[(size_t)i * Nc + j] * __expf(v[g] - mx);
            v[g] = e; s += e;
        }
        #pragma unroll
        for (int off = 16; off; off >>= 1) s += __shfl_xor_sync(0xffffffffu, s, off);
        const float inv = 1.f / s;
        #pragma unroll
        for (int g = 0; g < 12; g++) {
            const int j = lane + 32 * g;
            outb[(size_t)i * Nc + j] = v[g] * inv + 1e-10f;
        }
    }
}

// ----------------------------------------------------------------- launch
// GEMM1: 128x128 CTA, 8 warps (4x2), K=256  -> grid (8,24)=192
// GEMM2: 128x64 CTA, 8 warps (4x2), K=1024  -> grid (4,24)=96
#define SMEM1 (1024 + 2 * (2 * 128 * 80 + 2 * 128 * 80))   // 82944
#define SMEM2 (1024 + 2 * (2 * 128 * 80 + 2 * 64 * 80))    // 62464

extern "C" void kernel_launch(void* const* d_in, const int* in_sizes, int n_in,
                              void* d_out, int out_size)
{
    const float* x       = (const float*)d_in[0];
    const float* adj     = (const float*)d_in[1];
    const int*   box_num = (const int*)d_in[2];
    const float* fc1_w   = (const float*)d_in[3];
    const float* fc1_b   = (const float*)d_in[4];
    const float* fc2_w   = (const float*)d_in[5];
    const float* fc2_b   = (const float*)d_in[6];
    const float* learn_w = (const float*)d_in[7];

    float* soft = (float*)d_out;                   // [8,384,384]
    float* xhat = soft + (size_t)Bc * Nc * Nc;     // [8,384,256]

    static __nv_bfloat16 *xhi, *xlo, *w1hi, *w1lo, *w2hi, *w2lo, *hhi, *hlo;
    static bool init = false;
    if (!init) {
        cudaGetSymbolAddress((void**)&xhi,  g_xhi);
        cudaGetSymbolAddress((void**)&xlo,  g_xlo);
        cudaGetSymbolAddress((void**)&w1hi, g_w1hi);
        cudaGetSymbolAddress((void**)&w1lo, g_w1lo);
        cudaGetSymbolAddress((void**)&w2hi, g_w2hi);
        cudaGetSymbolAddress((void**)&w2lo, g_w2lo);
        cudaGetSymbolAddress((void**)&hhi,  g_hhi);
        cudaGetSymbolAddress((void**)&hlo,  g_hlo);
        cudaFuncSetAttribute((const void*)mma_gemm<128,128,8,4,Dc,1>,
                             cudaFuncAttributeMaxDynamicSharedMemorySize, SMEM1);
        cudaFuncSetAttribute((const void*)mma_gemm<128,64,8,4,Hc,2>,
                             cudaFuncAttributeMaxDynamicSharedMemorySize, SMEM2);
        cudaFuncSetAttribute((const void*)dist_kernel,
                             cudaFuncAttributeMaxDynamicSharedMemorySize,
                             (24 * Dc + 2 * Nc * XJ_STR) * 4);
        init = true;
    }

    prep_kernel<<<N4TOT / 512, 512>>>(x, fc1_w, fc2_w, learn_w);

    mma_gemm<128,128,8,4,Dc,1><<<dim3(Hc/128, MR/128), 256, SMEM1>>>(
        xhi, xlo, w1hi, w1lo, fc1_b, nullptr, nullptr);
    mma_gemm<128,64,8,4,Hc,2><<<dim3(Dc/64, MR/128), 256, SMEM2>>>(
        hhi, hlo, w2hi, w2lo, fc2_b, learn_w, xhat);

    const int shm = (24 * Dc + 2 * Nc * XJ_STR) * 4;
    dist_kernel<<<dim3(Nc / 24, Bc), 384, shm>>>(adj, box_num, soft);
}

// round 7
// speedup vs baseline: 2.4713x; 1.0980x over previous
#include <cuda_runtime.h>
#include <cuda_bf16.h>
#include <cstdint>
#include <cstddef>

#define Bc 8
#define Nc 384
#define Dc 256
#define Hc 1024
#define MR (Bc*Nc)   // 3072

// ----------------------------------------------------------------- scratch
__device__ __align__(128) float g_y[(size_t)MR * Dc];
__device__ __align__(128) float g_S[MR];           // row sums of g_y
__device__ float g_sumw;
__device__ __align__(128) __nv_bfloat16 g_xhi[(size_t)MR * Dc],  g_xlo[(size_t)MR * Dc];
__device__ __align__(128) __nv_bfloat16 g_w1hi[(size_t)Hc * Dc], g_w1lo[(size_t)Hc * Dc];
__device__ __align__(128) __nv_bfloat16 g_w2hi[(size_t)Dc * Hc], g_w2lo[(size_t)Dc * Hc];
__device__ __align__(128) __nv_bfloat16 g_hhi[(size_t)MR * Hc],  g_hlo[(size_t)MR * Hc];

// ----------------------------------------------------------------- helpers
__device__ __forceinline__ uint32_t smem_u32(const void* p) {
    uint32_t a;
    asm("{ .reg .u64 t; cvta.to.shared.u64 t, %1; cvt.u32.u64 %0, t; }" : "=r"(a) : "l"(p));
    return a;
}
__device__ __forceinline__ void cp_async16(uint32_t dst, const void* src) {
    asm volatile("cp.async.cg.shared.global [%0], [%1], 16;\n" :: "r"(dst), "l"(src));
}
#define CP_COMMIT()  asm volatile("cp.async.commit_group;\n" ::: "memory")
#define CP_WAIT0()   asm volatile("cp.async.wait_group 0;\n" ::: "memory")
#define CP_WAIT1()   asm volatile("cp.async.wait_group 1;\n" ::: "memory")

__device__ __forceinline__ void ldsm_x4(uint32_t* r, uint32_t addr) {
    asm volatile("ldmatrix.sync.aligned.m8n8.x4.shared.b16 {%0,%1,%2,%3}, [%4];"
        : "=r"(r[0]), "=r"(r[1]), "=r"(r[2]), "=r"(r[3]) : "r"(addr));
}
__device__ __forceinline__ void mma_bf16(float* c, const uint32_t* a, const uint32_t* b) {
    asm volatile(
        "mma.sync.aligned.m16n8k16.row.col.f32.bf16.bf16.f32 "
        "{%0,%1,%2,%3}, {%4,%5,%6,%7}, {%8,%9}, {%0,%1,%2,%3};"
        : "+f"(c[0]), "+f"(c[1]), "+f"(c[2]), "+f"(c[3])
        : "r"(a[0]), "r"(a[1]), "r"(a[2]), "r"(a[3]), "r"(b[0]), "r"(b[1]));
}
__device__ __forceinline__ uint32_t cvt_bf16x2(float hi, float lo) {
    uint32_t r; asm("cvt.rn.bf16x2.f32 %0, %1, %2;" : "=r"(r) : "f"(hi), "f"(lo)); return r;
}

// ----------------------------------------------------------------- fused prep
#define N4X ((MR * Dc) / 4)      // 196608
#define N4W ((Hc * Dc) / 4)      // 65536
#define N4TOT (N4X + 2 * N4W)    // 327680

__global__ __launch_bounds__(512) void prep_kernel(
    const float* __restrict__ x, const float* __restrict__ w1,
    const float* __restrict__ w2, const float* __restrict__ lw)
{
    const int gid = blockIdx.x * 512 + threadIdx.x;

    const float* src;
    __nv_bfloat16 *hi, *lo;
    int idx;
    if (gid < N4X)            { src = x;  hi = g_xhi;  lo = g_xlo;  idx = gid; }
    else if (gid < N4X + N4W) { src = w1; hi = g_w1hi; lo = g_w1lo; idx = gid - N4X; }
    else                      { src = w2; hi = g_w2hi; lo = g_w2lo; idx = gid - N4X - N4W; }

    const float4 v = *(const float4*)(src + 4 * (size_t)idx);
    uint2 hw, lw4;
    hw.x = cvt_bf16x2(v.y, v.x);
    hw.y = cvt_bf16x2(v.w, v.z);
    {
        const float h0 = __uint_as_float(hw.x << 16);
        const float h1 = __uint_as_float(hw.x & 0xffff0000u);
        const float h2 = __uint_as_float(hw.y << 16);
        const float h3 = __uint_as_float(hw.y & 0xffff0000u);
        lw4.x = cvt_bf16x2(v.y - h1, v.x - h0);
        lw4.y = cvt_bf16x2(v.w - h3, v.z - h2);
    }
    *(uint2*)(hi + 4 * (size_t)idx) = hw;
    *(uint2*)(lo + 4 * (size_t)idx) = lw4;

    if (gid < MR) g_S[gid] = 0.f;   // zero row-sum accumulators

    if (blockIdx.x == 0 && threadIdx.x < 256) {
        __shared__ float sm[8];
        const int t = threadIdx.x;
        float s = lw[t];
        #pragma unroll
        for (int off = 16; off; off >>= 1) s += __shfl_xor_sync(0xffffffffu, s, off);
        if ((t & 31) == 0) sm[t >> 5] = s;
        __syncthreads();
        if (t == 0) {
            float acc = 0.f;
            #pragma unroll
            for (int k = 0; k < 8; k++) acc += sm[k];
            g_sumw = acc;
        }
    }
}

// ----------------------------------------------------------------- mma.sync GEMM
// C[M,N] = A[M,K] @ B[N,K]^T with 3-term bf16 hi/lo split, fp32 accum.
// EPI=1: relu -> hidden hi/lo bf16.  EPI=2: xhat fp32 + y=xhat*w + row-sum S atomics.
template<int BM, int BN, int NW, int WMF, int K, int EPI>
__global__ void __launch_bounds__(NW * 32) mma_gemm(
    const __nv_bfloat16* __restrict__ Ahi, const __nv_bfloat16* __restrict__ Alo,
    const __nv_bfloat16* __restrict__ Bhi, const __nv_bfloat16* __restrict__ Blo,
    const float* __restrict__ bias, const float* __restrict__ wvec,
    float* __restrict__ out)
{
    constexpr int NT  = NW * 32;
    constexpr int WN  = BN / (NW / WMF);
    constexpr int NN  = WN / 8;
    constexpr int TA  = BM * 80;
    constexpr int TB  = BN * 80;
    constexpr int BUF = 2 * TA + 2 * TB;
    constexpr int NCH = K / 32;
    constexpr int OUTD = (EPI == 1) ? Hc : Dc;

    extern __shared__ __align__(1024) char smem[];
    float* s_bias = (float*)smem;
    float* s_w    = (float*)(smem + BN * 4);
    const uint32_t tiles = smem_u32(smem) + 1024;

    const int tid  = threadIdx.x;
    const int wid  = tid >> 5, lane = tid & 31;
    const int m0   = blockIdx.y * BM, n0 = blockIdx.x * BN;
    const int wm   = (wid % WMF) * 32;
    const int wn   = (wid / WMF) * WN;

    if (tid < BN) {
        s_bias[tid] = bias[n0 + tid];
        if (EPI == 2) s_w[tid] = wvec[n0 + tid];
    }

    float cacc[2][NN][4];
    #pragma unroll
    for (int f = 0; f < 2; f++)
        #pragma unroll
        for (int g = 0; g < NN; g++)
            #pragma unroll
            for (int e = 0; e < 4; e++) cacc[f][g][e] = 0.f;

    auto issue = [&](int c) {
        const uint32_t tb = tiles + (c & 1) * BUF;
        const int kc = c * 32;
        #pragma unroll
        for (int q = 0; q < (BM * 8) / NT; ++q) {
            const int id = q * NT + tid;
            const int mat = id / (BM * 4), e = id % (BM * 4);
            const int r = e >> 2, c16 = e & 3;
            const __nv_bfloat16* src = (mat ? Alo : Ahi) + (size_t)(m0 + r) * K + kc + c16 * 8;
            cp_async16(tb + mat * TA + r * 80 + c16 * 16, src);
        }
        #pragma unroll
        for (int q = 0; q < (BN * 8) / NT; ++q) {
            const int id = q * NT + tid;
            const int mat = id / (BN * 4), e = id % (BN * 4);
            const int r = e >> 2, c16 = e & 3;
            const __nv_bfloat16* src = (mat ? Blo : Bhi) + (size_t)(n0 + r) * K + kc + c16 * 8;
            cp_async16(tb + 2 * TA + mat * TB + r * 80 + c16 * 16, src);
        }
        CP_COMMIT();
    };

    issue(0);
    issue(1);

    for (int c = 0; c < NCH; ++c) {
        if (c + 1 < NCH) { CP_WAIT1(); } else { CP_WAIT0(); }
        __syncthreads();

        const uint32_t aBase = tiles + (c & 1) * BUF;
        const uint32_t bBase = aBase + 2 * TA;

        #pragma unroll
        for (int s = 0; s < 2; ++s) {
            const int kk = s * 16;
            uint32_t aH[2][4], aL[2][4];
            #pragma unroll
            for (int f = 0; f < 2; ++f) {
                const int row = wm + f * 16 + (lane & 15);
                const int col = kk + ((lane >> 4) << 3);
                const uint32_t ad = aBase + row * 80 + col * 2;
                ldsm_x4(aH[f], ad);
                ldsm_x4(aL[f], ad + TA);
            }
            #pragma unroll
            for (int np = 0; np < NN / 2; ++np) {
                const int rowB = wn + np * 16 + (lane & 7) + ((lane & 16) >> 1);
                const int colB = kk + (lane & 8);
                const uint32_t bd = bBase + rowB * 80 + colB * 2;
                uint32_t bH[4], bL[4];
                ldsm_x4(bH, bd);
                ldsm_x4(bL, bd + TB);
                #pragma unroll
                for (int f = 0; f < 2; ++f) {
                    #pragma unroll
                    for (int h = 0; h < 2; ++h) {
                        float* cc = cacc[f][2 * np + h];
                        mma_bf16(cc, aH[f], bH + 2 * h);
                        mma_bf16(cc, aH[f], bL + 2 * h);
                        mma_bf16(cc, aL[f], bH + 2 * h);
                    }
                }
            }
        }
        __syncthreads();
        if (c + 2 < NCH) issue(c + 2);
    }

    // ------------------------------------------------------------- epilogue
    const int tq = lane >> 2, tr = lane & 3;
    float rs[2][2] = {{0.f, 0.f}, {0.f, 0.f}};
    #pragma unroll
    for (int f = 0; f < 2; ++f) {
        #pragma unroll
        for (int g = 0; g < NN; ++g) {
            const int col  = n0 + wn + g * 8 + tr * 2;
            const int bcol = wn + g * 8 + tr * 2;
            #pragma unroll
            for (int half = 0; half < 2; ++half) {
                const int row = m0 + wm + f * 16 + tq + half * 8;
                float v0 = cacc[f][g][2 * half]     + s_bias[bcol];
                float v1 = cacc[f][g][2 * half + 1] + s_bias[bcol + 1];
                if (EPI == 1) {
                    v0 = fmaxf(v0, 0.f); v1 = fmaxf(v1, 0.f);
                    const uint32_t h = cvt_bf16x2(v1, v0);
                    const float h0 = __uint_as_float(h << 16);
                    const float h1 = __uint_as_float(h & 0xffff0000u);
                    const uint32_t l = cvt_bf16x2(v1 - h1, v0 - h0);
                    *(uint32_t*)&g_hhi[(size_t)row * OUTD + col] = h;
                    *(uint32_t*)&g_hlo[(size_t)row * OUTD + col] = l;
                } else {
                    float2 o; o.x = v0; o.y = v1;
                    float2 yv; yv.x = v0 * s_w[bcol]; yv.y = v1 * s_w[bcol + 1];
                    *(float2*)&out[(size_t)row * OUTD + col] = o;
                    *(float2*)&g_y[(size_t)row * OUTD + col] = yv;
                    rs[f][half] += yv.x + yv.y;
                }
            }
        }
    }
    if (EPI == 2) {
        #pragma unroll
        for (int f = 0; f < 2; ++f)
            #pragma unroll
            for (int half = 0; half < 2; ++half) {
                float s = rs[f][half];
                s += __shfl_xor_sync(0xffffffffu, s, 1);
                s += __shfl_xor_sync(0xffffffffu, s, 2);
                if (tr == 0) {
                    const int row = m0 + wm + f * 16 + tq + half * 8;
                    atomicAdd(&g_S[row], s);
                }
            }
    }
}

// ----------------------------------------------------------------- dist
// dist(i,j) = S_i + S_j - 2*sum_d min(y_i,d , y_j,d)
// 384 threads: 12 warps x 2 rows x 12 col-groups. 24 rows/block, 128 blocks.
#define XJ_STR 36

__global__ __launch_bounds__(384) void dist_kernel(
    const float* __restrict__ adj,
    const int* __restrict__ box_num,
    float* __restrict__ out)
{
    extern __shared__ __align__(16) float sm[];
    float* s_xi = sm;                  // [24][256]
    float* s_S  = sm + 24 * Dc;        // [384] row sums for this batch
    float* s_xj = s_S + Nc;            // [2][384][XJ_STR]

    const int tid = threadIdx.x;
    const int b  = blockIdx.y;
    const int i0 = blockIdx.x * 24;
    const float* yb = g_y + (size_t)b * Nc * Dc;

    #pragma unroll
    for (int p = 0; p < 4; p++) {
        int q = tid + 384 * p;
        int i = q >> 6, c4 = (q & 63) << 2;
        *(float4*)&s_xi[i * Dc + c4] = *(const float4*)&yb[(size_t)(i0 + i) * Dc + c4];
    }
    s_S[tid] = g_S[b * Nc + tid];

    const uint32_t xj_addr = smem_u32(s_xj);

    #pragma unroll
    for (int p = 0; p < 8; p++) {
        int id = tid + 384 * p;
        int j = id >> 3, u = id & 7;
        cp_async16(xj_addr + (uint32_t)((j * XJ_STR + u * 4) << 2),
                   &yb[(size_t)j * Dc + u * 4]);
    }
    CP_COMMIT();

    float acc[2][12];
    #pragma unroll
    for (int r = 0; r < 2; r++)
        #pragma unroll
        for (int g = 0; g < 12; g++) acc[r][g] = 0.f;

    const int lane = tid & 31, ty = tid >> 5;
    const int ib = ty * 2;

    for (int c = 0; c < 8; c++) {
        if (c < 7) {
            uint32_t base = xj_addr + (uint32_t)(((c + 1) & 1) * (Nc * XJ_STR * 4));
            #pragma unroll
            for (int p = 0; p < 8; p++) {
                int id = tid + 384 * p;
                int j = id >> 3, u = id & 7;
                cp_async16(base + (uint32_t)((j * XJ_STR + u * 4) << 2),
                           &yb[(size_t)j * Dc + (c + 1) * 32 + u * 4]);
            }
            CP_COMMIT();
            CP_WAIT1();
        } else {
            CP_WAIT0();
        }
        __syncthreads();

        const float* xjc = s_xj + (c & 1) * (Nc * XJ_STR);
        #pragma unroll
        for (int d4 = 0; d4 < 8; d4++) {
            const int dof = c * 32 + d4 * 4;
            const float4 x0 = *(const float4*)&s_xi[(ib + 0) * Dc + dof];
            const float4 x1 = *(const float4*)&s_xi[(ib + 1) * Dc + dof];
            #pragma unroll
            for (int g = 0; g < 12; g++) {
                const float4 xv = *(const float4*)&xjc[(lane + 32 * g) * XJ_STR + d4 * 4];
                float a0 = acc[0][g], a1 = acc[1][g];
                a0 += fminf(x0.x, xv.x); a0 += fminf(x0.y, xv.y);
                a0 += fminf(x0.z, xv.z); a0 += fminf(x0.w, xv.w);
                a1 += fminf(x1.x, xv.x); a1 += fminf(x1.y, xv.y);
                a1 += fminf(x1.z, xv.z); a1 += fminf(x1.w, xv.w);
                acc[0][g] = a0; acc[1][g] = a1;
            }
        }
        __syncthreads();
    }

    const int bn = box_num[b];
    const float sumw = g_sumw;
    const float* adjb = adj + (size_t)b * Nc * Nc;
    float* outb = out + (size_t)b * Nc * Nc;

    #pragma unroll
    for (int r = 0; r < 2; r++) {
        const int i = i0 + ib + r;
        const bool vi = i < bn;
        const float si = s_S[i];
        float v[12];
        float mx = -3.4e38f;
        #pragma unroll
        for (int g = 0; g < 12; g++) {
            const int j = lane + 32 * g;
            float t = si + s_S[j] - 2.f * acc[r][g];
            if (!(vi && (j < bn))) t -= sumw;
            t = (t >= 0.f) ? t : 0.01f * t;
            v[g] = t;
            mx = fmaxf(mx, t);
        }
        #pragma unroll
        for (int off = 16; off; off >>= 1) mx = fmaxf(mx, __shfl_xor_sync(0xffffffffu, mx, off));
        float s = 0.f;
        #pragma unroll
        for (int g = 0; g < 12; g++) {
            const int j = lane + 32 * g;
            const float e = adjb[(size_t)i * Nc + j] * __expf(v[g] - mx);
            v[g] = e; s += e;
        }
        #pragma unroll
        for (int off = 16; off; off >>= 1) s += __shfl_xor_sync(0xffffffffu, s, off);
        const float inv = 1.f / s;
        #pragma unroll
        for (int g = 0; g < 12; g++) {
            const int j = lane + 32 * g;
            outb[(size_t)i * Nc + j] = v[g] * inv + 1e-10f;
        }
    }
}

// ----------------------------------------------------------------- launch
// GEMM1: 64x128 CTA, 4 warps (2x2), K=256  -> grid (8,48)=384, 2 CTAs/SM
// GEMM2: 128x64 CTA, 8 warps (4x2), K=1024 -> grid (4,24)=96
#define SMEM1 (1024 + 2 * (2 * 64 * 80 + 2 * 128 * 80))   // 62464
#define SMEM2 (1024 + 2 * (2 * 128 * 80 + 2 * 64 * 80))   // 62464
#define SMEMD ((24 * Dc + Nc + 2 * Nc * XJ_STR) * 4)

extern "C" void kernel_launch(void* const* d_in, const int* in_sizes, int n_in,
                              void* d_out, int out_size)
{
    const float* x       = (const float*)d_in[0];
    const float* adj     = (const float*)d_in[1];
    const int*   box_num = (const int*)d_in[2];
    const float* fc1_w   = (const float*)d_in[3];
    const float* fc1_b   = (const float*)d_in[4];
    const float* fc2_w   = (const float*)d_in[5];
    const float* fc2_b   = (const float*)d_in[6];
    const float* learn_w = (const float*)d_in[7];

    float* soft = (float*)d_out;                   // [8,384,384]
    float* xhat = soft + (size_t)Bc * Nc * Nc;     // [8,384,256]

    static __nv_bfloat16 *xhi, *xlo, *w1hi, *w1lo, *w2hi, *w2lo, *hhi, *hlo;
    static bool init = false;
    if (!init) {
        cudaGetSymbolAddress((void**)&xhi,  g_xhi);
        cudaGetSymbolAddress((void**)&xlo,  g_xlo);
        cudaGetSymbolAddress((void**)&w1hi, g_w1hi);
        cudaGetSymbolAddress((void**)&w1lo, g_w1lo);
        cudaGetSymbolAddress((void**)&w2hi, g_w2hi);
        cudaGetSymbolAddress((void**)&w2lo, g_w2lo);
        cudaGetSymbolAddress((void**)&hhi,  g_hhi);
        cudaGetSymbolAddress((void**)&hlo,  g_hlo);
        cudaFuncSetAttribute((const void*)mma_gemm<64,128,4,2,Dc,1>,
                             cudaFuncAttributeMaxDynamicSharedMemorySize, SMEM1);
        cudaFuncSetAttribute((const void*)mma_gemm<128,64,8,4,Hc,2>,
                             cudaFuncAttributeMaxDynamicSharedMemorySize, SMEM2);
        cudaFuncSetAttribute((const void*)dist_kernel,
                             cudaFuncAttributeMaxDynamicSharedMemorySize, SMEMD);
        init = true;
    }

    prep_kernel<<<N4TOT / 512, 512>>>(x, fc1_w, fc2_w, learn_w);

    mma_gemm<64,128,4,2,Dc,1><<<dim3(Hc/128, MR/64), 128, SMEM1>>>(
        xhi, xlo, w1hi, w1lo, fc1_b, nullptr, nullptr);
    mma_gemm<128,64,8,4,Hc,2><<<dim3(Dc/64, MR/128), 256, SMEM2>>>(
        hhi, hlo, w2hi, w2lo, fc2_b, learn_w, xhat);

    dist_kernel<<<dim3(Nc / 24, Bc), 384, SMEMD>>>(adj, box_num, soft);
}